// round 1
// baseline (speedup 1.0000x reference)
#include <cuda_runtime.h>

// ---------------------------------------------------------------------------
// Problem constants
// ---------------------------------------------------------------------------
#define Bsz  8
#define Sq   4096
#define Ltxt 77
#define Limg 16
#define Dm   1280
#define Cm   2048
#define Hh   20
#define DHd  64
#define Mbig (Bsz * Sq)          // 32768 rows for the two big GEMMs

// ---------------------------------------------------------------------------
// Scratch (allocation-free rule: __device__ globals)
// ---------------------------------------------------------------------------
__device__ float g_Q[(size_t)Mbig * Dm];        // 32768 x 1280
__device__ float g_O[(size_t)Mbig * Dm];        // summed attention output
__device__ float g_Ktxt[Bsz * Ltxt * Dm];
__device__ float g_Vtxt[Bsz * Ltxt * Dm];
__device__ float g_Kid [Bsz * Limg * Dm];
__device__ float g_Vid [Bsz * Limg * Dm];
__device__ float g_Khair[Bsz * Limg * Dm];
__device__ float g_Vhair[Bsz * Limg * Dm];

// ---------------------------------------------------------------------------
// Packed f32x2 helpers (sm_100+/sm_103a): 2x fp32 FMA per issue slot
// ---------------------------------------------------------------------------
__device__ __forceinline__ unsigned long long pk2(float lo, float hi) {
    unsigned long long r;
    asm("mov.b64 %0, {%1, %2};" : "=l"(r) : "f"(lo), "f"(hi));
    return r;
}
__device__ __forceinline__ void fma2(unsigned long long& d,
                                     unsigned long long a,
                                     unsigned long long b) {
    asm("fma.rn.f32x2 %0, %1, %2, %0;" : "+l"(d) : "l"(a), "l"(b));
}
__device__ __forceinline__ void upk2(unsigned long long v, float& lo, float& hi) {
    asm("mov.b64 {%0, %1}, %2;" : "=f"(lo), "=f"(hi) : "l"(v));
}

// ---------------------------------------------------------------------------
// fp32 GEMM body: C[M,N] = A[M,K] * B[K,N] (+bias), row-major everywhere.
// 128x128 block tile, BK=16, 256 threads, 8x8 microtile held as 8x4 f32x2.
// ---------------------------------------------------------------------------
__device__ __forceinline__ void gemm_body(
    const float* __restrict__ A, const float* __restrict__ B,
    const float* __restrict__ bias, float* __restrict__ C,
    int M, int K, int N, int bx, int by)
{
    __shared__ __align__(16) float As[16][128];   // A tile, transposed [k][m]
    __shared__ __align__(16) float Bs[16][128];   // B tile [k][n]

    const int tid = threadIdx.x;
    const int tx  = tid & 15;          // 0..15 -> 8 output cols each
    const int ty  = tid >> 4;          // 0..15 -> 8 output rows each
    const int row0 = by * 128;
    const int col0 = bx * 128;

    unsigned long long cc[8][4];
#pragma unroll
    for (int i = 0; i < 8; i++)
#pragma unroll
        for (int p = 0; p < 4; p++) cc[i][p] = 0ull;

    for (int kt = 0; kt < K; kt += 16) {
        // --- load A tile (128 rows x 16 k), stored transposed ---
#pragma unroll
        for (int li = 0; li < 2; li++) {
            int idx = tid * 2 + li;            // 0..511 float4s
            int r   = idx >> 2;                // row within tile 0..127
            int kq  = (idx & 3) * 4;           // k offset 0,4,8,12
            int grow = row0 + r;
            float4 av = make_float4(0.f, 0.f, 0.f, 0.f);
            if (grow < M)
                av = *(const float4*)(A + (size_t)grow * K + kt + kq);
            As[kq + 0][r] = av.x;
            As[kq + 1][r] = av.y;
            As[kq + 2][r] = av.z;
            As[kq + 3][r] = av.w;
        }
        // --- load B tile (16 k x 128 cols) ---
#pragma unroll
        for (int li = 0; li < 2; li++) {
            int idx = tid * 2 + li;            // 0..511 float4s
            int r   = idx >> 5;                // k row 0..15
            int c   = (idx & 31) * 4;          // col offset
            *(float4*)&Bs[r][c] =
                *(const float4*)(B + (size_t)(kt + r) * N + col0 + c);
        }
        __syncthreads();

#pragma unroll
        for (int k = 0; k < 16; k++) {
            float4 a0 = *(const float4*)&As[k][ty * 8];
            float4 a1 = *(const float4*)&As[k][ty * 8 + 4];
            ulonglong2 bv0 = *(const ulonglong2*)&Bs[k][tx * 8];
            ulonglong2 bv1 = *(const ulonglong2*)&Bs[k][tx * 8 + 4];
            unsigned long long br[4] = {bv0.x, bv0.y, bv1.x, bv1.y};
            float ar[8] = {a0.x, a0.y, a0.z, a0.w, a1.x, a1.y, a1.z, a1.w};
#pragma unroll
            for (int i = 0; i < 8; i++) {
                unsigned long long a2 = pk2(ar[i], ar[i]);
#pragma unroll
                for (int p = 0; p < 4; p++) fma2(cc[i][p], a2, br[p]);
            }
        }
        __syncthreads();
    }

    // --- epilogue ---
#pragma unroll
    for (int i = 0; i < 8; i++) {
        int grow = row0 + ty * 8 + i;
        if (grow >= M) continue;
        float ov[8];
#pragma unroll
        for (int p = 0; p < 4; p++) upk2(cc[i][p], ov[2 * p], ov[2 * p + 1]);
        int gc = col0 + tx * 8;
        if (bias) {
#pragma unroll
            for (int j = 0; j < 8; j++) ov[j] += bias[gc + j];
        }
        *(float4*)(C + (size_t)grow * N + gc) =
            make_float4(ov[0], ov[1], ov[2], ov[3]);
        *(float4*)(C + (size_t)grow * N + gc + 4) =
            make_float4(ov[4], ov[5], ov[6], ov[7]);
    }
}

// ---------------------------------------------------------------------------
// GEMM wrappers
// ---------------------------------------------------------------------------
__global__ void __launch_bounds__(256)
q_gemm_kernel(const float* __restrict__ hidden, const float* __restrict__ Wq) {
    gemm_body(hidden, Wq, nullptr, g_Q, Mbig, Dm, Dm, blockIdx.x, blockIdx.y);
}

__global__ void __launch_bounds__(256)
out_gemm_kernel(const float* __restrict__ Wo, const float* __restrict__ bo,
                float* __restrict__ out) {
    gemm_body(g_O, Wo, bo, out, Mbig, Dm, Dm, blockIdx.x, blockIdx.y);
}

// All 6 K/V projections in ONE launch (z selects which) so they fill one wave
// instead of serializing 6 tiny underutilized launches.
__global__ void __launch_bounds__(256)
kv_gemm_kernel(const float* __restrict__ text, const float* __restrict__ ids,
               const float* __restrict__ hair,
               const float* __restrict__ Wk,  const float* __restrict__ Wv,
               const float* __restrict__ Wki, const float* __restrict__ Wvi,
               const float* __restrict__ Wkh, const float* __restrict__ Wvh) {
    int z = blockIdx.z;
    const float* A; const float* Bw; float* Cc; int M;
    switch (z) {
        case 0:  A = text; Bw = Wk;  Cc = g_Ktxt;  M = Bsz * Ltxt; break;
        case 1:  A = text; Bw = Wv;  Cc = g_Vtxt;  M = Bsz * Ltxt; break;
        case 2:  A = ids;  Bw = Wki; Cc = g_Kid;   M = Bsz * Limg; break;
        case 3:  A = ids;  Bw = Wvi; Cc = g_Vid;   M = Bsz * Limg; break;
        case 4:  A = hair; Bw = Wkh; Cc = g_Khair; M = Bsz * Limg; break;
        default: A = hair; Bw = Wvh; Cc = g_Vhair; M = Bsz * Limg; break;
    }
    if (blockIdx.y * 128 >= M) return;   // uniform per block
    gemm_body(A, Bw, nullptr, Cc, M, Cm, Dm, blockIdx.x, blockIdx.y);
}

// ---------------------------------------------------------------------------
// Fused 3-branch attention. Block = (32 queries, one (b,h)). All three
// branches accumulate into registers; g_O written once (no +=-RMW traffic).
// ---------------------------------------------------------------------------
template <int NM>
__device__ __forceinline__ void attn_scores(const float (*Qs)[65],
                                            const float* KV,
                                            float (*Ps)[81],
                                            int lane, int w) {
    // thread computes scores (q = lane, j = w + 8m), m < NM.
    // KV is zero-padded to 80 rows, so no bounds checks in the hot loop.
    float acc[NM];
#pragma unroll
    for (int m = 0; m < NM; m++) acc[m] = 0.f;
#pragma unroll 8
    for (int d = 0; d < 64; d++) {
        float qv = Qs[lane][d];              // conflict-free (odd pad 65)
#pragma unroll
        for (int m = 0; m < NM; m++)
            acc[m] = fmaf(qv, KV[(w + 8 * m) * 64 + d], acc[m]);  // broadcast
    }
    const float scale = 0.125f;              // 1/sqrt(64)
#pragma unroll
    for (int m = 0; m < NM; m++) Ps[lane][w + 8 * m] = acc[m] * scale;
}

__global__ void __launch_bounds__(256) attn_kernel() {
    __shared__ __align__(16) float Qs[32][65];
    __shared__ __align__(16) float KV[80 * 64];   // K tile, then V tile
    __shared__ float Ps[32][81];

    const int tid  = threadIdx.x;
    const int lane = tid & 31;
    const int w    = tid >> 5;
    const int q0   = blockIdx.x * 32;
    const int bh   = blockIdx.y;
    const int b    = bh / Hh;
    const int h    = bh % Hh;

    // load Q tile [32 x 64]
    {
        int q  = tid >> 3;
        int dd = (tid & 7) * 8;
        const float* src = g_Q + ((size_t)(b * Sq + q0 + q)) * Dm + h * DHd + dd;
        float4 v0 = *(const float4*)src;
        float4 v1 = *(const float4*)(src + 4);
        Qs[q][dd + 0] = v0.x; Qs[q][dd + 1] = v0.y;
        Qs[q][dd + 2] = v0.z; Qs[q][dd + 3] = v0.w;
        Qs[q][dd + 4] = v1.x; Qs[q][dd + 5] = v1.y;
        Qs[q][dd + 6] = v1.z; Qs[q][dd + 7] = v1.w;
    }

    float o[8];
#pragma unroll
    for (int i = 0; i < 8; i++) o[i] = 0.f;

    const float* Kptrs[3] = {g_Ktxt, g_Kid, g_Khair};
    const float* Vptrs[3] = {g_Vtxt, g_Vid, g_Vhair};
    const int    Lvals[3] = {Ltxt, Limg, Limg};

#pragma unroll 1
    for (int br = 0; br < 3; br++) {
        const int L = Lvals[br];
        const float* Kp = Kptrs[br];
        const float* Vp = Vptrs[br];

        __syncthreads();   // Qs ready / KV+Ps free from previous branch

        // load K tile, zero-padded to 80 rows
        for (int i = tid; i < 80 * 16; i += 256) {
            int l = i >> 4;
            int c = (i & 15) * 4;
            float4 v = make_float4(0.f, 0.f, 0.f, 0.f);
            if (l < L)
                v = *(const float4*)(Kp + ((size_t)(b * L + l)) * Dm + h * DHd + c);
            *(float4*)&KV[l * 64 + c] = v;
        }
        __syncthreads();

        if (L > 16) attn_scores<10>(Qs, KV, Ps, lane, w);
        else        attn_scores<2>(Qs, KV, Ps, lane, w);
        __syncthreads();

        // softmax over j < L : 8 threads per query row
        {
            int q   = tid >> 3;
            int sub = tid & 7;
            float mx = -1e30f;
            for (int j = sub; j < L; j += 8) mx = fmaxf(mx, Ps[q][j]);
#pragma unroll
            for (int off = 1; off < 8; off <<= 1)
                mx = fmaxf(mx, __shfl_xor_sync(0xffffffffu, mx, off));
            float s = 0.f;
            for (int j = sub; j < L; j += 8) {
                float e = __expf(Ps[q][j] - mx);
                Ps[q][j] = e;
                s += e;
            }
#pragma unroll
            for (int off = 1; off < 8; off <<= 1)
                s += __shfl_xor_sync(0xffffffffu, s, off);
            float inv = 1.f / s;
            for (int j = sub; j < L; j += 8) Ps[q][j] *= inv;
        }
        __syncthreads();

        // load V tile (rows >= L never read by the bounded PV loop)
        for (int i = tid; i < L * 16; i += 256) {
            int l = i >> 4;
            int c = (i & 15) * 4;
            *(float4*)&KV[l * 64 + c] =
                *(const float4*)(Vp + ((size_t)(b * L + l)) * Dm + h * DHd + c);
        }
        __syncthreads();

        // o[q][d] += sum_j P[q][j] * V[j][d]; thread owns (q = tid&31, 8 d's)
        {
            int q  = tid & 31;
            int dw = (tid >> 5) * 8;
            for (int j = 0; j < L; j++) {
                float p = Ps[q][j];                          // conflict-free (pad 81)
                float4 v0 = *(const float4*)&KV[j * 64 + dw];      // broadcast
                float4 v1 = *(const float4*)&KV[j * 64 + dw + 4];
                o[0] = fmaf(p, v0.x, o[0]); o[1] = fmaf(p, v0.y, o[1]);
                o[2] = fmaf(p, v0.z, o[2]); o[3] = fmaf(p, v0.w, o[3]);
                o[4] = fmaf(p, v1.x, o[4]); o[5] = fmaf(p, v1.y, o[5]);
                o[6] = fmaf(p, v1.z, o[6]); o[7] = fmaf(p, v1.w, o[7]);
            }
        }
    }

    // write summed branch output once
    {
        int q  = tid & 31;
        int dw = (tid >> 5) * 8;
        float* dst = g_O + ((size_t)(b * Sq + q0 + q)) * Dm + h * DHd + dw;
        *(float4*)dst       = make_float4(o[0], o[1], o[2], o[3]);
        *(float4*)(dst + 4) = make_float4(o[4], o[5], o[6], o[7]);
    }
}

// ---------------------------------------------------------------------------
// kernel_launch: 4 graph-capturable launches on the default stream
// ---------------------------------------------------------------------------
extern "C" void kernel_launch(void* const* d_in, const int* in_sizes, int n_in,
                              void* d_out, int out_size) {
    const float* hidden = (const float*)d_in[0];
    const float* text   = (const float*)d_in[1];
    const float* ids    = (const float*)d_in[2];
    const float* hair   = (const float*)d_in[3];
    const float* Wq     = (const float*)d_in[4];
    const float* Wk     = (const float*)d_in[5];
    const float* Wv     = (const float*)d_in[6];
    const float* Wo     = (const float*)d_in[7];
    const float* bo     = (const float*)d_in[8];
    const float* Wk_id  = (const float*)d_in[9];
    const float* Wv_id  = (const float*)d_in[10];
    const float* Wk_h   = (const float*)d_in[11];
    const float* Wv_h   = (const float*)d_in[12];
    float* out = (float*)d_out;

    // 1) all six K/V projections in one wave
    kv_gemm_kernel<<<dim3(Dm / 128, 5, 6), 256>>>(
        text, ids, hair, Wk, Wv, Wk_id, Wv_id, Wk_h, Wv_h);

    // 2) Q = hidden @ Wq
    q_gemm_kernel<<<dim3(Dm / 128, Mbig / 128), 256>>>(hidden, Wq);

    // 3) fused 3-branch attention -> g_O (sum of branches)
    attn_kernel<<<dim3(Sq / 32, Bsz * Hh), 256>>>();

    // 4) out = g_O @ Wo + bo   (single output GEMM thanks to shared Wo)
    out_gemm_kernel<<<dim3(Dm / 128, Mbig / 128), 256>>>(Wo, bo, out);
}

// round 3
// speedup vs baseline: 1.9103x; 1.9103x over previous
#include <cuda_runtime.h>
#include <cuda_bf16.h>
#include <cstdint>

// ---------------------------------------------------------------------------
// Problem constants
// ---------------------------------------------------------------------------
#define Bsz  8
#define Sq   4096
#define Ltxt 77
#define Limg 16
#define Dm   1280
#define Cm   2048
#define Hh   20
#define DHd  64
#define Mbig (Bsz * Sq)          // 32768
#define Mtxt (Bsz * Ltxt)        // 616
#define Mimg (Bsz * Limg)        // 128

// ---------------------------------------------------------------------------
// Scratch (__device__ globals; no allocation allowed)
// ---------------------------------------------------------------------------
__device__ float g_Q[(size_t)Mbig * Dm];
__device__ float g_Ktxt[Mtxt * Dm];
__device__ float g_Vtxt[Mtxt * Dm];
__device__ float g_Kid [Mimg * Dm];
__device__ float g_Vid [Mimg * Dm];
__device__ float g_Khair[Mimg * Dm];
__device__ float g_Vhair[Mimg * Dm];

// bf16 hi/lo splits of activations (A operands, [M][K] row-major)
__device__ __nv_bfloat16 g_Ahi[(size_t)Mbig * Dm], g_Alo[(size_t)Mbig * Dm];
__device__ __nv_bfloat16 g_Ohi[(size_t)Mbig * Dm], g_Olo[(size_t)Mbig * Dm];
__device__ __nv_bfloat16 g_Thi[(size_t)Mtxt * Cm], g_Tlo[(size_t)Mtxt * Cm];
__device__ __nv_bfloat16 g_Ihi[(size_t)Mimg * Cm], g_Ilo[(size_t)Mimg * Cm];
__device__ __nv_bfloat16 g_Hhi[(size_t)Mimg * Cm], g_Hlo[(size_t)Mimg * Cm];

// transposed + split weights: Wt[n][k] bf16 (B operands)
__device__ __nv_bfloat16 g_WtQ_hi[Dm * Dm],  g_WtQ_lo[Dm * Dm];
__device__ __nv_bfloat16 g_WtO_hi[Dm * Dm],  g_WtO_lo[Dm * Dm];
__device__ __nv_bfloat16 g_WtKV_hi[6][(size_t)Dm * Cm];
__device__ __nv_bfloat16 g_WtKV_lo[6][(size_t)Dm * Cm];

// ---------------------------------------------------------------------------
// Helpers
// ---------------------------------------------------------------------------
__device__ __forceinline__ uint32_t smem_u32(const void* p) {
    uint32_t a;
    asm("{ .reg .u64 t; cvta.to.shared.u64 t, %1; cvt.u32.u64 %0, t; }"
        : "=r"(a) : "l"(p));
    return a;
}
__device__ __forceinline__ void split1(float v, __nv_bfloat16& h, __nv_bfloat16& l) {
    h = __float2bfloat16_rn(v);
    l = __float2bfloat16_rn(v - __bfloat162float(h));
}
__device__ __forceinline__ void cpa16(uint32_t dst, const void* src, bool p) {
    int sz = p ? 16 : 0;
    asm volatile("cp.async.cg.shared.global [%0], [%1], 16, %2;"
                 :: "r"(dst), "l"(src), "r"(sz));
}
__device__ __forceinline__ void ldm4(uint32_t* r, uint32_t addr) {
    asm volatile("ldmatrix.sync.aligned.m8n8.x4.shared.b16 {%0,%1,%2,%3}, [%4];"
                 : "=r"(r[0]), "=r"(r[1]), "=r"(r[2]), "=r"(r[3]) : "r"(addr));
}
__device__ __forceinline__ void mma16816(float* d, const uint32_t* a,
                                         uint32_t b0, uint32_t b1) {
    asm volatile(
        "mma.sync.aligned.m16n8k16.row.col.f32.bf16.bf16.f32 "
        "{%0,%1,%2,%3}, {%4,%5,%6,%7}, {%8,%9}, {%0,%1,%2,%3};"
        : "+f"(d[0]), "+f"(d[1]), "+f"(d[2]), "+f"(d[3])
        : "r"(a[0]), "r"(a[1]), "r"(a[2]), "r"(a[3]), "r"(b0), "r"(b1));
}

// ---------------------------------------------------------------------------
// Weight transpose + split:  W[K,N=1280] fp32  ->  Wt_hi/lo[N,K] bf16
// ---------------------------------------------------------------------------
__global__ void __launch_bounds__(256)
transpose_split_kernel(const float* __restrict__ Wq, const float* __restrict__ Wo,
                       const float* __restrict__ Wk,  const float* __restrict__ Wv,
                       const float* __restrict__ Wki, const float* __restrict__ Wvi,
                       const float* __restrict__ Wkh, const float* __restrict__ Wvh) {
    const float* W; __nv_bfloat16* Hi; __nv_bfloat16* Lo; int K;
    switch (blockIdx.z) {
        case 0: W = Wq;  Hi = g_WtQ_hi;     Lo = g_WtQ_lo;     K = Dm; break;
        case 1: W = Wo;  Hi = g_WtO_hi;     Lo = g_WtO_lo;     K = Dm; break;
        case 2: W = Wk;  Hi = g_WtKV_hi[0]; Lo = g_WtKV_lo[0]; K = Cm; break;
        case 3: W = Wv;  Hi = g_WtKV_hi[1]; Lo = g_WtKV_lo[1]; K = Cm; break;
        case 4: W = Wki; Hi = g_WtKV_hi[2]; Lo = g_WtKV_lo[2]; K = Cm; break;
        case 5: W = Wvi; Hi = g_WtKV_hi[3]; Lo = g_WtKV_lo[3]; K = Cm; break;
        case 6: W = Wkh; Hi = g_WtKV_hi[4]; Lo = g_WtKV_lo[4]; K = Cm; break;
        default:W = Wvh; Hi = g_WtKV_hi[5]; Lo = g_WtKV_lo[5]; K = Cm; break;
    }
    int k0 = blockIdx.y * 32;
    if (k0 >= K) return;
    int n0 = blockIdx.x * 32;

    __shared__ float ts[32][33];
    int tx = threadIdx.x & 31;
    int ty = threadIdx.x >> 5;
#pragma unroll
    for (int j = 0; j < 4; j++)
        ts[ty + j * 8][tx] = W[(size_t)(k0 + ty + j * 8) * Dm + n0 + tx];
    __syncthreads();
#pragma unroll
    for (int j = 0; j < 4; j++) {
        int nn = ty + j * 8;
        __nv_bfloat16 h, l;
        split1(ts[tx][nn], h, l);
        size_t off = (size_t)(n0 + nn) * K + k0 + tx;
        Hi[off] = h;
        Lo[off] = l;
    }
}

// ---------------------------------------------------------------------------
// Activation split:  fp32 [n] -> hi/lo bf16
// ---------------------------------------------------------------------------
__global__ void __launch_bounds__(256)
split_inputs_kernel(const float* __restrict__ hidden, const float* __restrict__ text,
                    const float* __restrict__ ids,    const float* __restrict__ hair) {
    const float* src; __nv_bfloat16* hi; __nv_bfloat16* lo; size_t n;
    switch (blockIdx.z) {
        case 0:  src = hidden; hi = g_Ahi; lo = g_Alo; n = (size_t)Mbig * Dm; break;
        case 1:  src = text;   hi = g_Thi; lo = g_Tlo; n = (size_t)Mtxt * Cm; break;
        case 2:  src = ids;    hi = g_Ihi; lo = g_Ilo; n = (size_t)Mimg * Cm; break;
        default: src = hair;   hi = g_Hhi; lo = g_Hlo; n = (size_t)Mimg * Cm; break;
    }
    size_t n4 = n >> 2;
    for (size_t i = (size_t)blockIdx.x * 256 + threadIdx.x; i < n4;
         i += (size_t)gridDim.x * 256) {
        float4 v = ((const float4*)src)[i];
        __nv_bfloat16 h0, h1, h2, h3, l0, l1, l2, l3;
        split1(v.x, h0, l0); split1(v.y, h1, l1);
        split1(v.z, h2, l2); split1(v.w, h3, l3);
        __nv_bfloat162 ha = __halves2bfloat162(h0, h1);
        __nv_bfloat162 hb = __halves2bfloat162(h2, h3);
        __nv_bfloat162 la = __halves2bfloat162(l0, l1);
        __nv_bfloat162 lb = __halves2bfloat162(l2, l3);
        uint2 hp, lp;
        hp.x = *(uint32_t*)&ha; hp.y = *(uint32_t*)&hb;
        lp.x = *(uint32_t*)&la; lp.y = *(uint32_t*)&lb;
        *(uint2*)(hi + i * 4) = hp;
        *(uint2*)(lo + i * 4) = lp;
    }
}

// ---------------------------------------------------------------------------
// Warp-MMA bf16 3-pass GEMM: C[M,1280] = (Ahi+Alo)[M,K] @ (Wthi+Wtlo)[1280,K]^T
// 128x128 tile, BK=32, 8 warps (64x32 each), cp.async double buffer.
// ---------------------------------------------------------------------------
#define BM 128
#define BN 128
#define BKB 32
#define ROWB 80                 // padded SMEM row stride in bytes (64 data + 16)
#define A_HI 0
#define A_LO 10240
#define B_HI 20480
#define B_LO 30720
#define STAGE_B 40960
#define GSMEM (2 * STAGE_B)

__device__ __forceinline__ void mma_gemm_body(
    const __nv_bfloat16* __restrict__ Ahi, const __nv_bfloat16* __restrict__ Alo,
    const __nv_bfloat16* __restrict__ Bhi, const __nv_bfloat16* __restrict__ Blo,
    const float* __restrict__ bias, float* __restrict__ C,
    int M, int K, int bx, int by)
{
    extern __shared__ __align__(128) char smem[];
    const int tid  = threadIdx.x;
    const int lane = tid & 31;
    const int wid  = tid >> 5;
    const int wm   = wid & 1;          // 2 warp rows
    const int wn   = wid >> 1;         // 4 warp cols
    const int row0 = by * BM;
    const int col0 = bx * BN;
    const int nch  = K / BKB;

    float acc[4][4][4];
#pragma unroll
    for (int a = 0; a < 4; a++)
#pragma unroll
        for (int b = 0; b < 4; b++)
#pragma unroll
            for (int d = 0; d < 4; d++) acc[a][b][d] = 0.f;

    // stage loader: A hi/lo + B hi/lo, 16B cp.async each
    auto ld_stage = [&](int c, int s) {
        uint32_t base = smem_u32(smem + s * STAGE_B);
        int k0 = c * BKB;
#pragma unroll
        for (int i = 0; i < 2; i++) {
            int lin = i * 256 + tid;       // 0..511
            int r   = lin >> 2;            // tile row 0..127
            int sg  = lin & 3;             // 16B segment in row
            uint32_t d = base + r * ROWB + sg * 16;
            // A (bounds-checked on M)
            int grow = row0 + r;
            bool p = grow < M;
            int ga = p ? grow : (M - 1);
            size_t aoff = (size_t)ga * K + k0 + sg * 8;
            cpa16(d + A_HI, Ahi + aoff, p);
            cpa16(d + A_LO, Alo + aoff, p);
            // B (always in range: N = 1280 divisible)
            size_t boff = (size_t)(col0 + r) * K + k0 + sg * 8;
            cpa16(d + B_HI, Bhi + boff, true);
            cpa16(d + B_LO, Blo + boff, true);
        }
    };

    auto compute = [&](int s) {
        uint32_t sb = smem_u32(smem + s * STAGE_B);
        uint32_t aB = sb + (wm * 64) * ROWB;
        uint32_t bB = sb + B_HI + (wn * 32) * ROWB;
        uint32_t lrow  = lane & 15;
        uint32_t lhalf = (lane >> 4) * 16;
#pragma unroll
        for (int ks = 0; ks < 2; ks++) {
            uint32_t bh[2][4], bl[2][4];
#pragma unroll
            for (int ng = 0; ng < 2; ng++) {
                uint32_t ad = bB + (ng * 16 + lrow) * ROWB + ks * 32 + lhalf;
                ldm4(bh[ng], ad);
                ldm4(bl[ng], ad + 10240);
            }
#pragma unroll
            for (int mt = 0; mt < 4; mt++) {
                uint32_t ah[4], al[4];
                uint32_t ad = aB + (mt * 16 + lrow) * ROWB + ks * 32 + lhalf;
                ldm4(ah, ad);
                ldm4(al, ad + 10240);
#pragma unroll
                for (int j = 0; j < 4; j++) {
                    int ng = j >> 1, q = j & 1;
                    mma16816(acc[mt][j], ah, bh[ng][q], bh[ng][q + 2]);
                    mma16816(acc[mt][j], ah, bl[ng][q], bl[ng][q + 2]);
                    mma16816(acc[mt][j], al, bh[ng][q], bh[ng][q + 2]);
                }
            }
        }
    };

    ld_stage(0, 0);
    asm volatile("cp.async.commit_group;" ::: "memory");
    for (int c = 0; c < nch; c++) {
        int s = c & 1;
        if (c + 1 < nch) {
            ld_stage(c + 1, s ^ 1);
            asm volatile("cp.async.commit_group;" ::: "memory");
            asm volatile("cp.async.wait_group 1;" ::: "memory");
        } else {
            asm volatile("cp.async.wait_group 0;" ::: "memory");
        }
        __syncthreads();
        compute(s);
        __syncthreads();
    }

    // epilogue
    const int tg = lane >> 2, tq = lane & 3;
#pragma unroll
    for (int mt = 0; mt < 4; mt++) {
        int r0 = row0 + wm * 64 + mt * 16 + tg;
        int r1 = r0 + 8;
#pragma unroll
        for (int j = 0; j < 4; j++) {
            int col = col0 + wn * 32 + j * 8 + tq * 2;
            float b0 = 0.f, b1 = 0.f;
            if (bias) { b0 = bias[col]; b1 = bias[col + 1]; }
            if (r0 < M)
                *(float2*)(C + (size_t)r0 * Dm + col) =
                    make_float2(acc[mt][j][0] + b0, acc[mt][j][1] + b1);
            if (r1 < M)
                *(float2*)(C + (size_t)r1 * Dm + col) =
                    make_float2(acc[mt][j][2] + b0, acc[mt][j][3] + b1);
        }
    }
}

__global__ void __launch_bounds__(256, 2)
gemm_q_kernel() {
    mma_gemm_body(g_Ahi, g_Alo, g_WtQ_hi, g_WtQ_lo, nullptr, g_Q,
                  Mbig, Dm, blockIdx.x, blockIdx.y);
}
__global__ void __launch_bounds__(256, 2)
gemm_out_kernel(const float* __restrict__ bo, float* __restrict__ out) {
    mma_gemm_body(g_Ohi, g_Olo, g_WtO_hi, g_WtO_lo, bo, out,
                  Mbig, Dm, blockIdx.x, blockIdx.y);
}
__global__ void __launch_bounds__(256, 2)
gemm_kv_kernel() {
    int z = blockIdx.z;
    const __nv_bfloat16 *ah, *al; float* Cc; int M;
    switch (z) {
        case 0:  ah = g_Thi; al = g_Tlo; Cc = g_Ktxt;  M = Mtxt; break;
        case 1:  ah = g_Thi; al = g_Tlo; Cc = g_Vtxt;  M = Mtxt; break;
        case 2:  ah = g_Ihi; al = g_Ilo; Cc = g_Kid;   M = Mimg; break;
        case 3:  ah = g_Ihi; al = g_Ilo; Cc = g_Vid;   M = Mimg; break;
        case 4:  ah = g_Hhi; al = g_Hlo; Cc = g_Khair; M = Mimg; break;
        default: ah = g_Hhi; al = g_Hlo; Cc = g_Vhair; M = Mimg; break;
    }
    if (blockIdx.y * BM >= M) return;
    mma_gemm_body(ah, al, g_WtKV_hi[z], g_WtKV_lo[z], nullptr, Cc,
                  M, Cm, blockIdx.x, blockIdx.y);
}

// ---------------------------------------------------------------------------
// Fused 3-branch attention; epilogue writes hi/lo bf16 into g_Ohi/g_Olo.
// ---------------------------------------------------------------------------
template <int NM>
__device__ __forceinline__ void attn_scores(const float (*Qs)[65],
                                            const float* KV,
                                            float (*Ps)[81],
                                            int lane, int w) {
    float acc[NM];
#pragma unroll
    for (int m = 0; m < NM; m++) acc[m] = 0.f;
#pragma unroll 8
    for (int d = 0; d < 64; d++) {
        float qv = Qs[lane][d];
#pragma unroll
        for (int m = 0; m < NM; m++)
            acc[m] = fmaf(qv, KV[(w + 8 * m) * 64 + d], acc[m]);
    }
    const float scale = 0.125f;
#pragma unroll
    for (int m = 0; m < NM; m++) Ps[lane][w + 8 * m] = acc[m] * scale;
}

__global__ void __launch_bounds__(256) attn_kernel() {
    __shared__ __align__(16) float Qs[32][65];
    __shared__ __align__(16) float KV[80 * 64];
    __shared__ float Ps[32][81];

    const int tid  = threadIdx.x;
    const int lane = tid & 31;
    const int w    = tid >> 5;
    const int q0   = blockIdx.x * 32;
    const int bh   = blockIdx.y;
    const int b    = bh / Hh;
    const int h    = bh % Hh;

    {
        int q  = tid >> 3;
        int dd = (tid & 7) * 8;
        const float* src = g_Q + ((size_t)(b * Sq + q0 + q)) * Dm + h * DHd + dd;
        float4 v0 = *(const float4*)src;
        float4 v1 = *(const float4*)(src + 4);
        Qs[q][dd + 0] = v0.x; Qs[q][dd + 1] = v0.y;
        Qs[q][dd + 2] = v0.z; Qs[q][dd + 3] = v0.w;
        Qs[q][dd + 4] = v1.x; Qs[q][dd + 5] = v1.y;
        Qs[q][dd + 6] = v1.z; Qs[q][dd + 7] = v1.w;
    }

    float o[8];
#pragma unroll
    for (int i = 0; i < 8; i++) o[i] = 0.f;

    const float* Kptrs[3] = {g_Ktxt, g_Kid, g_Khair};
    const float* Vptrs[3] = {g_Vtxt, g_Vid, g_Vhair};
    const int    Lvals[3] = {Ltxt, Limg, Limg};

#pragma unroll 1
    for (int br = 0; br < 3; br++) {
        const int L = Lvals[br];
        const float* Kp = Kptrs[br];
        const float* Vp = Vptrs[br];

        __syncthreads();

        for (int i = tid; i < 80 * 16; i += 256) {
            int l = i >> 4;
            int c = (i & 15) * 4;
            float4 v = make_float4(0.f, 0.f, 0.f, 0.f);
            if (l < L)
                v = *(const float4*)(Kp + ((size_t)(b * L + l)) * Dm + h * DHd + c);
            *(float4*)&KV[l * 64 + c] = v;
        }
        __syncthreads();

        if (L > 16) attn_scores<10>(Qs, KV, Ps, lane, w);
        else        attn_scores<2>(Qs, KV, Ps, lane, w);
        __syncthreads();

        {
            int q   = tid >> 3;
            int sub = tid & 7;
            float mx = -1e30f;
            for (int j = sub; j < L; j += 8) mx = fmaxf(mx, Ps[q][j]);
#pragma unroll
            for (int off = 1; off < 8; off <<= 1)
                mx = fmaxf(mx, __shfl_xor_sync(0xffffffffu, mx, off));
            float s = 0.f;
            for (int j = sub; j < L; j += 8) {
                float e = __expf(Ps[q][j] - mx);
                Ps[q][j] = e;
                s += e;
            }
#pragma unroll
            for (int off = 1; off < 8; off <<= 1)
                s += __shfl_xor_sync(0xffffffffu, s, off);
            float inv = 1.f / s;
            for (int j = sub; j < L; j += 8) Ps[q][j] *= inv;
        }
        __syncthreads();

        for (int i = tid; i < L * 16; i += 256) {
            int l = i >> 4;
            int c = (i & 15) * 4;
            *(float4*)&KV[l * 64 + c] =
                *(const float4*)(Vp + ((size_t)(b * L + l)) * Dm + h * DHd + c);
        }
        __syncthreads();

        {
            int q  = tid & 31;
            int dw = (tid >> 5) * 8;
            for (int j = 0; j < L; j++) {
                float p = Ps[q][j];
                float4 v0 = *(const float4*)&KV[j * 64 + dw];
                float4 v1 = *(const float4*)&KV[j * 64 + dw + 4];
                o[0] = fmaf(p, v0.x, o[0]); o[1] = fmaf(p, v0.y, o[1]);
                o[2] = fmaf(p, v0.z, o[2]); o[3] = fmaf(p, v0.w, o[3]);
                o[4] = fmaf(p, v1.x, o[4]); o[5] = fmaf(p, v1.y, o[5]);
                o[6] = fmaf(p, v1.z, o[6]); o[7] = fmaf(p, v1.w, o[7]);
            }
        }
    }

    // epilogue: write hi/lo bf16 (feeds out-GEMM A operand directly)
    {
        int q  = tid & 31;
        int dw = (tid >> 5) * 8;
        __nv_bfloat16 hv[8], lv[8];
#pragma unroll
        for (int i = 0; i < 8; i++) split1(o[i], hv[i], lv[i]);
        uint4 hp, lp;
        {
            __nv_bfloat162 a0 = __halves2bfloat162(hv[0], hv[1]);
            __nv_bfloat162 a1 = __halves2bfloat162(hv[2], hv[3]);
            __nv_bfloat162 a2 = __halves2bfloat162(hv[4], hv[5]);
            __nv_bfloat162 a3 = __halves2bfloat162(hv[6], hv[7]);
            hp.x = *(uint32_t*)&a0; hp.y = *(uint32_t*)&a1;
            hp.z = *(uint32_t*)&a2; hp.w = *(uint32_t*)&a3;
            __nv_bfloat162 c0 = __halves2bfloat162(lv[0], lv[1]);
            __nv_bfloat162 c1 = __halves2bfloat162(lv[2], lv[3]);
            __nv_bfloat162 c2 = __halves2bfloat162(lv[4], lv[5]);
            __nv_bfloat162 c3 = __halves2bfloat162(lv[6], lv[7]);
            lp.x = *(uint32_t*)&c0; lp.y = *(uint32_t*)&c1;
            lp.z = *(uint32_t*)&c2; lp.w = *(uint32_t*)&c3;
        }
        size_t off = ((size_t)(b * Sq + q0 + q)) * Dm + h * DHd + dw;
        *(uint4*)(g_Ohi + off) = hp;
        *(uint4*)(g_Olo + off) = lp;
    }
}

// ---------------------------------------------------------------------------
// kernel_launch
// ---------------------------------------------------------------------------
extern "C" void kernel_launch(void* const* d_in, const int* in_sizes, int n_in,
                              void* d_out, int out_size) {
    const float* hidden = (const float*)d_in[0];
    const float* text   = (const float*)d_in[1];
    const float* ids    = (const float*)d_in[2];
    const float* hair   = (const float*)d_in[3];
    const float* Wq     = (const float*)d_in[4];
    const float* Wk     = (const float*)d_in[5];
    const float* Wv     = (const float*)d_in[6];
    const float* Wo     = (const float*)d_in[7];
    const float* bo     = (const float*)d_in[8];
    const float* Wk_id  = (const float*)d_in[9];
    const float* Wv_id  = (const float*)d_in[10];
    const float* Wk_h   = (const float*)d_in[11];
    const float* Wv_h   = (const float*)d_in[12];
    float* out = (float*)d_out;

    cudaFuncSetAttribute(gemm_q_kernel,   cudaFuncAttributeMaxDynamicSharedMemorySize, GSMEM);
    cudaFuncSetAttribute(gemm_out_kernel, cudaFuncAttributeMaxDynamicSharedMemorySize, GSMEM);
    cudaFuncSetAttribute(gemm_kv_kernel,  cudaFuncAttributeMaxDynamicSharedMemorySize, GSMEM);

    // 1) transpose + split all 8 weight matrices -> Wt[n][k] hi/lo
    transpose_split_kernel<<<dim3(Dm / 32, Cm / 32, 8), 256>>>(
        Wq, Wo, Wk, Wv, Wk_id, Wv_id, Wk_h, Wv_h);

    // 2) split activations -> hi/lo bf16
    split_inputs_kernel<<<dim3(8192, 1, 4), 256>>>(hidden, text, ids, hair);

    // 3) Q = hidden @ Wq (warp MMA, fp32 out)
    gemm_q_kernel<<<dim3(Dm / BN, Mbig / BM), 256, GSMEM>>>();

    // 4) six K/V projections
    gemm_kv_kernel<<<dim3(Dm / BN, 5, 6), 256, GSMEM>>>();

    // 5) fused 3-branch attention -> g_Ohi/g_Olo (bf16 split)
    attn_kernel<<<dim3(Sq / 32, Bsz * Hh), 256>>>();

    // 6) out = O @ Wo + bo
    gemm_out_kernel<<<dim3(Dm / BN, Mbig / BM), 256, GSMEM>>>(bo, out);
}

// round 5
// speedup vs baseline: 1.9479x; 1.0197x over previous
#include <cuda_runtime.h>
#include <cuda_bf16.h>
#include <cstdint>

// ---------------------------------------------------------------------------
// Problem constants
// ---------------------------------------------------------------------------
#define Bsz  8
#define Sq   4096
#define Ltxt 77
#define Limg 16
#define Dm   1280
#define Cm   2048
#define Hh   20
#define DHd  64
#define Mbig (Bsz * Sq)          // 32768
#define Mtxt (Bsz * Ltxt)        // 616
#define Mimg (Bsz * Limg)        // 128

// ---------------------------------------------------------------------------
// Scratch (__device__ globals; no allocation allowed)
// ---------------------------------------------------------------------------
__device__ float g_Q[(size_t)Mbig * Dm];
__device__ float g_Ktxt[Mtxt * Dm];
__device__ float g_Vtxt[Mtxt * Dm];
__device__ float g_Kid [Mimg * Dm];
__device__ float g_Vid [Mimg * Dm];
__device__ float g_Khair[Mimg * Dm];
__device__ float g_Vhair[Mimg * Dm];

// bf16 hi/lo splits of activations (A operands, [M][K] row-major)
__device__ __nv_bfloat16 g_Ahi[(size_t)Mbig * Dm], g_Alo[(size_t)Mbig * Dm];
__device__ __nv_bfloat16 g_Ohi[(size_t)Mbig * Dm], g_Olo[(size_t)Mbig * Dm];
__device__ __nv_bfloat16 g_Thi[(size_t)Mtxt * Cm], g_Tlo[(size_t)Mtxt * Cm];
__device__ __nv_bfloat16 g_Ihi[(size_t)Mimg * Cm], g_Ilo[(size_t)Mimg * Cm];
__device__ __nv_bfloat16 g_Hhi[(size_t)Mimg * Cm], g_Hlo[(size_t)Mimg * Cm];

// transposed + split weights: Wt[n][k] bf16 (B operands)
__device__ __nv_bfloat16 g_WtQ_hi[Dm * Dm],  g_WtQ_lo[Dm * Dm];
__device__ __nv_bfloat16 g_WtO_hi[Dm * Dm],  g_WtO_lo[Dm * Dm];
__device__ __nv_bfloat16 g_WtKV_hi[6][(size_t)Dm * Cm];
__device__ __nv_bfloat16 g_WtKV_lo[6][(size_t)Dm * Cm];

// ---------------------------------------------------------------------------
// Helpers
// ---------------------------------------------------------------------------
__device__ __forceinline__ uint32_t smem_u32(const void* p) {
    uint32_t a;
    asm("{ .reg .u64 t; cvta.to.shared.u64 t, %1; cvt.u32.u64 %0, t; }"
        : "=r"(a) : "l"(p));
    return a;
}
__device__ __forceinline__ void split1(float v, __nv_bfloat16& h, __nv_bfloat16& l) {
    h = __float2bfloat16_rn(v);
    l = __float2bfloat16_rn(v - __bfloat162float(h));
}
__device__ __forceinline__ void cpa16(uint32_t dst, const void* src, bool p) {
    int sz = p ? 16 : 0;
    asm volatile("cp.async.cg.shared.global [%0], [%1], 16, %2;"
                 :: "r"(dst), "l"(src), "r"(sz));
}
__device__ __forceinline__ void ldm4(uint32_t* r, uint32_t addr) {
    asm volatile("ldmatrix.sync.aligned.m8n8.x4.shared.b16 {%0,%1,%2,%3}, [%4];"
                 : "=r"(r[0]), "=r"(r[1]), "=r"(r[2]), "=r"(r[3]) : "r"(addr));
}
__device__ __forceinline__ void mma16816(float* d, const uint32_t* a,
                                         uint32_t b0, uint32_t b1) {
    asm volatile(
        "mma.sync.aligned.m16n8k16.row.col.f32.bf16.bf16.f32 "
        "{%0,%1,%2,%3}, {%4,%5,%6,%7}, {%8,%9}, {%0,%1,%2,%3};"
        : "+f"(d[0]), "+f"(d[1]), "+f"(d[2]), "+f"(d[3])
        : "r"(a[0]), "r"(a[1]), "r"(a[2]), "r"(a[3]), "r"(b0), "r"(b1));
}
// packed f32x2 (sm_103a)
__device__ __forceinline__ unsigned long long pk2(float lo, float hi) {
    unsigned long long r;
    asm("mov.b64 %0, {%1, %2};" : "=l"(r) : "f"(lo), "f"(hi));
    return r;
}
__device__ __forceinline__ void fma2(unsigned long long& d,
                                     unsigned long long a,
                                     unsigned long long b) {
    asm("fma.rn.f32x2 %0, %1, %2, %0;" : "+l"(d) : "l"(a), "l"(b));
}
__device__ __forceinline__ void upk2(unsigned long long v, float& lo, float& hi) {
    asm("mov.b64 {%0, %1}, %2;" : "=f"(lo), "=f"(hi) : "l"(v));
}

// ---------------------------------------------------------------------------
// Weight transpose + split:  W[K,N=1280] fp32  ->  Wt_hi/lo[N,K] bf16
// ---------------------------------------------------------------------------
__global__ void __launch_bounds__(256)
transpose_split_kernel(const float* __restrict__ Wq, const float* __restrict__ Wo,
                       const float* __restrict__ Wk,  const float* __restrict__ Wv,
                       const float* __restrict__ Wki, const float* __restrict__ Wvi,
                       const float* __restrict__ Wkh, const float* __restrict__ Wvh) {
    const float* W; __nv_bfloat16* Hi; __nv_bfloat16* Lo; int K;
    switch (blockIdx.z) {
        case 0: W = Wq;  Hi = g_WtQ_hi;     Lo = g_WtQ_lo;     K = Dm; break;
        case 1: W = Wo;  Hi = g_WtO_hi;     Lo = g_WtO_lo;     K = Dm; break;
        case 2: W = Wk;  Hi = g_WtKV_hi[0]; Lo = g_WtKV_lo[0]; K = Cm; break;
        case 3: W = Wv;  Hi = g_WtKV_hi[1]; Lo = g_WtKV_lo[1]; K = Cm; break;
        case 4: W = Wki; Hi = g_WtKV_hi[2]; Lo = g_WtKV_lo[2]; K = Cm; break;
        case 5: W = Wvi; Hi = g_WtKV_hi[3]; Lo = g_WtKV_lo[3]; K = Cm; break;
        case 6: W = Wkh; Hi = g_WtKV_hi[4]; Lo = g_WtKV_lo[4]; K = Cm; break;
        default:W = Wvh; Hi = g_WtKV_hi[5]; Lo = g_WtKV_lo[5]; K = Cm; break;
    }
    int k0 = blockIdx.y * 32;
    if (k0 >= K) return;
    int n0 = blockIdx.x * 32;

    __shared__ float ts[32][33];
    int tx = threadIdx.x & 31;
    int ty = threadIdx.x >> 5;
#pragma unroll
    for (int j = 0; j < 4; j++)
        ts[ty + j * 8][tx] = W[(size_t)(k0 + ty + j * 8) * Dm + n0 + tx];
    __syncthreads();
#pragma unroll
    for (int j = 0; j < 4; j++) {
        int nn = ty + j * 8;
        __nv_bfloat16 h, l;
        split1(ts[tx][nn], h, l);
        size_t off = (size_t)(n0 + nn) * K + k0 + tx;
        Hi[off] = h;
        Lo[off] = l;
    }
}

// ---------------------------------------------------------------------------
// Activation split:  fp32 [n] -> hi/lo bf16
// ---------------------------------------------------------------------------
__global__ void __launch_bounds__(256)
split_inputs_kernel(const float* __restrict__ hidden, const float* __restrict__ text,
                    const float* __restrict__ ids,    const float* __restrict__ hair) {
    const float* src; __nv_bfloat16* hi; __nv_bfloat16* lo; size_t n;
    switch (blockIdx.z) {
        case 0:  src = hidden; hi = g_Ahi; lo = g_Alo; n = (size_t)Mbig * Dm; break;
        case 1:  src = text;   hi = g_Thi; lo = g_Tlo; n = (size_t)Mtxt * Cm; break;
        case 2:  src = ids;    hi = g_Ihi; lo = g_Ilo; n = (size_t)Mimg * Cm; break;
        default: src = hair;   hi = g_Hhi; lo = g_Hlo; n = (size_t)Mimg * Cm; break;
    }
    size_t n4 = n >> 2;
    for (size_t i = (size_t)blockIdx.x * 256 + threadIdx.x; i < n4;
         i += (size_t)gridDim.x * 256) {
        float4 v = ((const float4*)src)[i];
        __nv_bfloat16 h0, h1, h2, h3, l0, l1, l2, l3;
        split1(v.x, h0, l0); split1(v.y, h1, l1);
        split1(v.z, h2, l2); split1(v.w, h3, l3);
        __nv_bfloat162 ha = __halves2bfloat162(h0, h1);
        __nv_bfloat162 hb = __halves2bfloat162(h2, h3);
        __nv_bfloat162 la = __halves2bfloat162(l0, l1);
        __nv_bfloat162 lb = __halves2bfloat162(l2, l3);
        uint2 hp, lp;
        hp.x = *(uint32_t*)&ha; hp.y = *(uint32_t*)&hb;
        lp.x = *(uint32_t*)&la; lp.y = *(uint32_t*)&lb;
        *(uint2*)(hi + i * 4) = hp;
        *(uint2*)(lo + i * 4) = lp;
    }
}

// ---------------------------------------------------------------------------
// Warp-MMA bf16 3-pass GEMM body (unchanged from R3)
// ---------------------------------------------------------------------------
#define BM 128
#define BN 128
#define BKB 32
#define ROWB 80
#define A_HI 0
#define A_LO 10240
#define B_HI 20480
#define B_LO 30720
#define STAGE_B 40960
#define GSMEM (2 * STAGE_B)

__device__ __forceinline__ void mma_gemm_body(
    const __nv_bfloat16* __restrict__ Ahi, const __nv_bfloat16* __restrict__ Alo,
    const __nv_bfloat16* __restrict__ Bhi, const __nv_bfloat16* __restrict__ Blo,
    const float* __restrict__ bias, float* __restrict__ C,
    int M, int K, int bx, int by)
{
    extern __shared__ __align__(128) char smem[];
    const int tid  = threadIdx.x;
    const int lane = tid & 31;
    const int wid  = tid >> 5;
    const int wm   = wid & 1;
    const int wn   = wid >> 1;
    const int row0 = by * BM;
    const int col0 = bx * BN;
    const int nch  = K / BKB;

    float acc[4][4][4];
#pragma unroll
    for (int a = 0; a < 4; a++)
#pragma unroll
        for (int b = 0; b < 4; b++)
#pragma unroll
            for (int d = 0; d < 4; d++) acc[a][b][d] = 0.f;

    auto ld_stage = [&](int c, int s) {
        uint32_t base = smem_u32(smem + s * STAGE_B);
        int k0 = c * BKB;
#pragma unroll
        for (int i = 0; i < 2; i++) {
            int lin = i * 256 + tid;
            int r   = lin >> 2;
            int sg  = lin & 3;
            uint32_t d = base + r * ROWB + sg * 16;
            int grow = row0 + r;
            bool p = grow < M;
            int ga = p ? grow : (M - 1);
            size_t aoff = (size_t)ga * K + k0 + sg * 8;
            cpa16(d + A_HI, Ahi + aoff, p);
            cpa16(d + A_LO, Alo + aoff, p);
            size_t boff = (size_t)(col0 + r) * K + k0 + sg * 8;
            cpa16(d + B_HI, Bhi + boff, true);
            cpa16(d + B_LO, Blo + boff, true);
        }
    };

    auto compute = [&](int s) {
        uint32_t sb = smem_u32(smem + s * STAGE_B);
        uint32_t aB = sb + (wm * 64) * ROWB;
        uint32_t bB = sb + B_HI + (wn * 32) * ROWB;
        uint32_t lrow  = lane & 15;
        uint32_t lhalf = (lane >> 4) * 16;
#pragma unroll
        for (int ks = 0; ks < 2; ks++) {
            uint32_t bh[2][4], bl[2][4];
#pragma unroll
            for (int ng = 0; ng < 2; ng++) {
                uint32_t ad = bB + (ng * 16 + lrow) * ROWB + ks * 32 + lhalf;
                ldm4(bh[ng], ad);
                ldm4(bl[ng], ad + 10240);
            }
#pragma unroll
            for (int mt = 0; mt < 4; mt++) {
                uint32_t ah[4], al[4];
                uint32_t ad = aB + (mt * 16 + lrow) * ROWB + ks * 32 + lhalf;
                ldm4(ah, ad);
                ldm4(al, ad + 10240);
#pragma unroll
                for (int j = 0; j < 4; j++) {
                    int ng = j >> 1, q = j & 1;
                    mma16816(acc[mt][j], ah, bh[ng][q], bh[ng][q + 2]);
                    mma16816(acc[mt][j], ah, bl[ng][q], bl[ng][q + 2]);
                    mma16816(acc[mt][j], al, bh[ng][q], bh[ng][q + 2]);
                }
            }
        }
    };

    ld_stage(0, 0);
    asm volatile("cp.async.commit_group;" ::: "memory");
    for (int c = 0; c < nch; c++) {
        int s = c & 1;
        if (c + 1 < nch) {
            ld_stage(c + 1, s ^ 1);
            asm volatile("cp.async.commit_group;" ::: "memory");
            asm volatile("cp.async.wait_group 1;" ::: "memory");
        } else {
            asm volatile("cp.async.wait_group 0;" ::: "memory");
        }
        __syncthreads();
        compute(s);
        __syncthreads();
    }

    const int tg = lane >> 2, tq = lane & 3;
#pragma unroll
    for (int mt = 0; mt < 4; mt++) {
        int r0 = row0 + wm * 64 + mt * 16 + tg;
        int r1 = r0 + 8;
#pragma unroll
        for (int j = 0; j < 4; j++) {
            int col = col0 + wn * 32 + j * 8 + tq * 2;
            float b0 = 0.f, b1 = 0.f;
            if (bias) { b0 = bias[col]; b1 = bias[col + 1]; }
            if (r0 < M)
                *(float2*)(C + (size_t)r0 * Dm + col) =
                    make_float2(acc[mt][j][0] + b0, acc[mt][j][1] + b1);
            if (r1 < M)
                *(float2*)(C + (size_t)r1 * Dm + col) =
                    make_float2(acc[mt][j][2] + b0, acc[mt][j][3] + b1);
        }
    }
}

// Merged Q + 6xKV GEMM: y<256 -> Q tiles; y-256 in [0,14) -> exact KV tiles.
__global__ void __launch_bounds__(256, 2)
gemm_qkv_kernel() {
    int y = blockIdx.y;
    if (y < 256) {
        mma_gemm_body(g_Ahi, g_Alo, g_WtQ_hi, g_WtQ_lo, nullptr, g_Q,
                      Mbig, Dm, blockIdx.x, y);
        return;
    }
    int yy = y - 256;
    const __nv_bfloat16 *ah, *al; float* Cc; int M, z, by;
    if (yy < 5)       { z = 0; by = yy;     ah = g_Thi; al = g_Tlo; Cc = g_Ktxt;  M = Mtxt; }
    else if (yy < 10) { z = 1; by = yy - 5; ah = g_Thi; al = g_Tlo; Cc = g_Vtxt;  M = Mtxt; }
    else if (yy == 10){ z = 2; by = 0;      ah = g_Ihi; al = g_Ilo; Cc = g_Kid;   M = Mimg; }
    else if (yy == 11){ z = 3; by = 0;      ah = g_Ihi; al = g_Ilo; Cc = g_Vid;   M = Mimg; }
    else if (yy == 12){ z = 4; by = 0;      ah = g_Hhi; al = g_Hlo; Cc = g_Khair; M = Mimg; }
    else              { z = 5; by = 0;      ah = g_Hhi; al = g_Hlo; Cc = g_Vhair; M = Mimg; }
    mma_gemm_body(ah, al, g_WtKV_hi[z], g_WtKV_lo[z], nullptr, Cc,
                  M, Cm, blockIdx.x, by);
}

__global__ void __launch_bounds__(256, 2)
gemm_out_kernel(const float* __restrict__ bo, float* __restrict__ out) {
    mma_gemm_body(g_Ohi, g_Olo, g_WtO_hi, g_WtO_lo, bo, out,
                  Mbig, Dm, blockIdx.x, blockIdx.y);
}

// ---------------------------------------------------------------------------
// Fused 3-branch attention — f32x2 packed FMA + 128-bit shared loads.
// ---------------------------------------------------------------------------
template <int NM>
__device__ __forceinline__ void attn_scores2(const float (*Qs)[68],
                                             const float* KV,
                                             float (*Ps)[81],
                                             int lane, int w) {
    // acc pairs accumulate {sum over even d, sum over odd d} for each j.
    unsigned long long acc[NM];
#pragma unroll
    for (int m = 0; m < NM; m++) acc[m] = 0ull;
#pragma unroll
    for (int d4 = 0; d4 < 16; d4++) {
        ulonglong2 qp = *(const ulonglong2*)&Qs[lane][d4 * 4];   // q[d..d+3]
#pragma unroll
        for (int m = 0; m < NM; m++) {
            ulonglong2 kp = *(const ulonglong2*)&KV[(w + 8 * m) * 64 + d4 * 4];
            fma2(acc[m], qp.x, kp.x);
            fma2(acc[m], qp.y, kp.y);
        }
    }
    const float scale = 0.125f;
#pragma unroll
    for (int m = 0; m < NM; m++) {
        float lo, hi;
        upk2(acc[m], lo, hi);
        Ps[lane][w + 8 * m] = (lo + hi) * scale;
    }
}

__global__ void __launch_bounds__(256) attn_kernel() {
    __shared__ __align__(16) float Qs[32][68];    // stride 68: 16B-aligned rows
    __shared__ __align__(16) float KV[80 * 64];
    __shared__ float Ps[32][81];

    const int tid  = threadIdx.x;
    const int lane = tid & 31;
    const int w    = tid >> 5;
    const int q0   = blockIdx.x * 32;
    const int bh   = blockIdx.y;
    const int b    = bh / Hh;
    const int h    = bh % Hh;

    {
        int q  = tid >> 3;
        int dd = (tid & 7) * 8;
        const float* src = g_Q + ((size_t)(b * Sq + q0 + q)) * Dm + h * DHd + dd;
        float4 v0 = *(const float4*)src;
        float4 v1 = *(const float4*)(src + 4);
        *(float4*)&Qs[q][dd]     = v0;
        *(float4*)&Qs[q][dd + 4] = v1;
    }

    // packed output accumulators: o2[i] = {o[2i], o[2i+1]}
    unsigned long long o2[4] = {0ull, 0ull, 0ull, 0ull};

    const float* Kptrs[3] = {g_Ktxt, g_Kid, g_Khair};
    const float* Vptrs[3] = {g_Vtxt, g_Vid, g_Vhair};
    const int    Lvals[3] = {Ltxt, Limg, Limg};

#pragma unroll 1
    for (int br = 0; br < 3; br++) {
        const int L = Lvals[br];
        const float* Kp = Kptrs[br];
        const float* Vp = Vptrs[br];

        __syncthreads();

        for (int i = tid; i < 80 * 16; i += 256) {
            int l = i >> 4;
            int c = (i & 15) * 4;
            float4 v = make_float4(0.f, 0.f, 0.f, 0.f);
            if (l < L)
                v = *(const float4*)(Kp + ((size_t)(b * L + l)) * Dm + h * DHd + c);
            *(float4*)&KV[l * 64 + c] = v;
        }
        __syncthreads();

        if (L > 16) attn_scores2<10>(Qs, KV, Ps, lane, w);
        else        attn_scores2<2>(Qs, KV, Ps, lane, w);
        __syncthreads();

        {
            int q   = tid >> 3;
            int sub = tid & 7;
            float mx = -1e30f;
            for (int j = sub; j < L; j += 8) mx = fmaxf(mx, Ps[q][j]);
#pragma unroll
            for (int off = 1; off < 8; off <<= 1)
                mx = fmaxf(mx, __shfl_xor_sync(0xffffffffu, mx, off));
            float s = 0.f;
            for (int j = sub; j < L; j += 8) {
                float e = __expf(Ps[q][j] - mx);
                Ps[q][j] = e;
                s += e;
            }
#pragma unroll
            for (int off = 1; off < 8; off <<= 1)
                s += __shfl_xor_sync(0xffffffffu, s, off);
            float inv = 1.f / s;
            for (int j = sub; j < L; j += 8) Ps[q][j] *= inv;
        }
        __syncthreads();

        for (int i = tid; i < L * 16; i += 256) {
            int l = i >> 4;
            int c = (i & 15) * 4;
            *(float4*)&KV[l * 64 + c] =
                *(const float4*)(Vp + ((size_t)(b * L + l)) * Dm + h * DHd + c);
        }
        __syncthreads();

        {
            int q  = tid & 31;
            int dw = (tid >> 5) * 8;
            for (int j = 0; j < L; j++) {
                unsigned long long pp = pk2(Ps[q][j], Ps[q][j]);
                ulonglong2 v0 = *(const ulonglong2*)&KV[j * 64 + dw];      // broadcast
                ulonglong2 v1 = *(const ulonglong2*)&KV[j * 64 + dw + 4];
                fma2(o2[0], pp, v0.x);
                fma2(o2[1], pp, v0.y);
                fma2(o2[2], pp, v1.x);
                fma2(o2[3], pp, v1.y);
            }
        }
    }

    // epilogue: unpack, split to hi/lo bf16 (feeds out-GEMM A operand)
    {
        float o[8];
#pragma unroll
        for (int i = 0; i < 4; i++) upk2(o2[i], o[2 * i], o[2 * i + 1]);
        int q  = tid & 31;
        int dw = (tid >> 5) * 8;
        __nv_bfloat16 hv[8], lv[8];
#pragma unroll
        for (int i = 0; i < 8; i++) split1(o[i], hv[i], lv[i]);
        uint4 hp, lp;
        {
            __nv_bfloat162 a0 = __halves2bfloat162(hv[0], hv[1]);
            __nv_bfloat162 a1 = __halves2bfloat162(hv[2], hv[3]);
            __nv_bfloat162 a2 = __halves2bfloat162(hv[4], hv[5]);
            __nv_bfloat162 a3 = __halves2bfloat162(hv[6], hv[7]);
            hp.x = *(uint32_t*)&a0; hp.y = *(uint32_t*)&a1;
            hp.z = *(uint32_t*)&a2; hp.w = *(uint32_t*)&a3;
            __nv_bfloat162 c0 = __halves2bfloat162(lv[0], lv[1]);
            __nv_bfloat162 c1 = __halves2bfloat162(lv[2], lv[3]);
            __nv_bfloat162 c2 = __halves2bfloat162(lv[4], lv[5]);
            __nv_bfloat162 c3 = __halves2bfloat162(lv[6], lv[7]);
            lp.x = *(uint32_t*)&c0; lp.y = *(uint32_t*)&c1;
            lp.z = *(uint32_t*)&c2; lp.w = *(uint32_t*)&c3;
        }
        size_t off = ((size_t)(b * Sq + q0 + q)) * Dm + h * DHd + dw;
        *(uint4*)(g_Ohi + off) = hp;
        *(uint4*)(g_Olo + off) = lp;
    }
}

// ---------------------------------------------------------------------------
// kernel_launch
// ---------------------------------------------------------------------------
extern "C" void kernel_launch(void* const* d_in, const int* in_sizes, int n_in,
                              void* d_out, int out_size) {
    const float* hidden = (const float*)d_in[0];
    const float* text   = (const float*)d_in[1];
    const float* ids    = (const float*)d_in[2];
    const float* hair   = (const float*)d_in[3];
    const float* Wq     = (const float*)d_in[4];
    const float* Wk     = (const float*)d_in[5];
    const float* Wv     = (const float*)d_in[6];
    const float* Wo     = (const float*)d_in[7];
    const float* bo     = (const float*)d_in[8];
    const float* Wk_id  = (const float*)d_in[9];
    const float* Wv_id  = (const float*)d_in[10];
    const float* Wk_h   = (const float*)d_in[11];
    const float* Wv_h   = (const float*)d_in[12];
    float* out = (float*)d_out;

    cudaFuncSetAttribute(gemm_qkv_kernel, cudaFuncAttributeMaxDynamicSharedMemorySize, GSMEM);
    cudaFuncSetAttribute(gemm_out_kernel, cudaFuncAttributeMaxDynamicSharedMemorySize, GSMEM);

    // 1) transpose + split all 8 weight matrices -> Wt[n][k] hi/lo
    transpose_split_kernel<<<dim3(Dm / 32, Cm / 32, 8), 256>>>(
        Wq, Wo, Wk, Wv, Wk_id, Wv_id, Wk_h, Wv_h);

    // 2) split activations -> hi/lo bf16
    split_inputs_kernel<<<dim3(8192, 1, 4), 256>>>(hidden, text, ids, hair);

    // 3) Q GEMM + all six K/V projections in ONE launch (KV fills Q's tail)
    gemm_qkv_kernel<<<dim3(Dm / BN, 256 + 14), 256, GSMEM>>>();

    // 4) fused 3-branch attention -> g_Ohi/g_Olo (bf16 split)
    attn_kernel<<<dim3(Sq / 32, Bsz * Hh), 256>>>();

    // 5) out = O @ Wo + bo
    gemm_out_kernel<<<dim3(Dm / BN, Mbig / BM), 256, GSMEM>>>(bo, out);
}